// round 1
// baseline (speedup 1.0000x reference)
#include <cuda_runtime.h>

#define BB   4
#define HH   16
#define SS   2048
#define HD   64
#define DIN  1024
#define DOUT 1024

// Scratch (allocation-free rule: __device__ globals)
__device__ float g_q[BB * HH * SS * HD];     // [B,H,S,HD]
__device__ float g_k[BB * HH * SS * HD];     // [B,H,S,HD]
__device__ float g_v[BB * HH * SS * HD];     // [B,H,S,HD]
__device__ float g_ctx[BB * SS * DOUT];      // [B,S,H*HD]

// ---------------------------------------------------------------------------
// QKV GEMM: X[8192,1024] @ W[1024,1024] -> [B,H,S,HD], blockIdx.z selects Q/K/V
// 64x64 output tile, BK=16, 256 threads, 4x4 per thread.
// ---------------------------------------------------------------------------
__global__ __launch_bounds__(256) void qkv_gemm_kernel(
    const float* __restrict__ x,
    const float* __restrict__ Wq,
    const float* __restrict__ Wk,
    const float* __restrict__ Wv)
{
    __shared__ float sA[16][65];   // A tile transposed [k][m], pad 65
    __shared__ float sB[16][64];   // B tile natural    [k][n]

    const float* W   = (blockIdx.z == 0) ? Wq : (blockIdx.z == 1) ? Wk : Wv;
    float*       out = (blockIdx.z == 0) ? g_q : (blockIdx.z == 1) ? g_k : g_v;

    const int tx = threadIdx.x, ty = threadIdx.y;
    const int tid = ty * 16 + tx;
    const int bm = blockIdx.x, bn = blockIdx.y;   // bn == head index

    const float* Arow = x + (bm * 64 + (tid >> 2)) * DIN + (tid & 3) * 4;
    const float* Brow = W + (tid >> 4) * DOUT + bn * 64 + (tid & 15) * 4;

    float acc[4][4] = {};

    for (int kt = 0; kt < DIN / 16; ++kt) {
        float4 av = *(const float4*)(Arow + kt * 16);
        float4 bv = *(const float4*)(Brow + kt * 16 * DOUT);

        __syncthreads();
        {
            int r = tid >> 2, c4 = (tid & 3) * 4;
            sA[c4 + 0][r] = av.x;
            sA[c4 + 1][r] = av.y;
            sA[c4 + 2][r] = av.z;
            sA[c4 + 3][r] = av.w;
            *(float4*)&sB[tid >> 4][(tid & 15) * 4] = bv;
        }
        __syncthreads();

        #pragma unroll
        for (int k = 0; k < 16; ++k) {
            float4 b4 = *(float4*)&sB[k][tx * 4];
            float a0 = sA[k][ty * 4 + 0];
            float a1 = sA[k][ty * 4 + 1];
            float a2 = sA[k][ty * 4 + 2];
            float a3 = sA[k][ty * 4 + 3];
            acc[0][0] += a0 * b4.x; acc[0][1] += a0 * b4.y; acc[0][2] += a0 * b4.z; acc[0][3] += a0 * b4.w;
            acc[1][0] += a1 * b4.x; acc[1][1] += a1 * b4.y; acc[1][2] += a1 * b4.z; acc[1][3] += a1 * b4.w;
            acc[2][0] += a2 * b4.x; acc[2][1] += a2 * b4.y; acc[2][2] += a2 * b4.z; acc[2][3] += a2 * b4.w;
            acc[3][0] += a3 * b4.x; acc[3][1] += a3 * b4.y; acc[3][2] += a3 * b4.z; acc[3][3] += a3 * b4.w;
        }
    }

    // Epilogue: write [B,H,S,HD]
    #pragma unroll
    for (int i = 0; i < 4; ++i) {
        int mm = bm * 64 + ty * 4 + i;
        int b = mm >> 11, s = mm & 2047;
        float4 r = make_float4(acc[i][0], acc[i][1], acc[i][2], acc[i][3]);
        *(float4*)&out[(((b * HH + bn) * SS + s) * HD) + tx * 4] = r;
    }
}

// ---------------------------------------------------------------------------
// Causal flash attention, fp32.  One block = (b, h, 64-query tile).
// 256 threads (16x16), 4x4 register blocking for both S=QK^T and O+=P*V.
// Online softmax in base-2 (0.125*log2e folded into Q).
// ---------------------------------------------------------------------------
#define PAD 68
#define ATTN_SMEM (4 * 64 * PAD * 4)

__global__ __launch_bounds__(256) void attn_kernel()
{
    extern __shared__ float sm[];
    float* sQ = sm;                 // [64][PAD]  d-major (transposed)
    float* sK = sm + 64 * PAD;      // [64][PAD]  d-major (transposed)
    float* sV = sm + 2 * 64 * PAD;  // [64][PAD]  key-major (natural)
    float* sP = sm + 3 * 64 * PAD;  // [64][PAD]  query-major

    const int qt = blockIdx.x, h = blockIdx.y, b = blockIdx.z;
    const float* qb = g_q + ((b * HH + h) * SS) * HD;
    const float* kb = g_k + ((b * HH + h) * SS) * HD;
    const float* vb = g_v + ((b * HH + h) * SS) * HD;

    const int tx = threadIdx.x, ty = threadIdx.y;
    const int tid = ty * 16 + tx;
    const float qscale = 0.125f * 1.4426950408889634f;  // 1/sqrt(64) * log2(e)

    // Load Q tile transposed (once)
    for (int off = tid; off < 4096; off += 256) {
        int d = off & 63, s = off >> 6;
        sQ[d * PAD + s] = qb[(qt * 64 + s) * HD + d] * qscale;
    }

    float o[4][4] = {};
    float mi[4] = {-1e30f, -1e30f, -1e30f, -1e30f};
    float li[4] = {};

    for (int jt = 0; jt <= qt; ++jt) {
        __syncthreads();   // prior iteration's reads of sK/sV/sP done
        for (int off = tid; off < 4096; off += 256) {
            int d = off & 63, s = off >> 6;
            int g = (jt * 64 + s) * HD + d;
            sK[d * PAD + s] = kb[g];
            sV[s * PAD + d] = vb[g];
        }
        __syncthreads();

        // S = Q K^T  (contraction over d)
        float acc[4][4] = {};
        #pragma unroll 8
        for (int dd = 0; dd < 64; ++dd) {
            float4 b4 = *(float4*)&sK[dd * PAD + tx * 4];
            float a0 = sQ[dd * PAD + ty * 4 + 0];
            float a1 = sQ[dd * PAD + ty * 4 + 1];
            float a2 = sQ[dd * PAD + ty * 4 + 2];
            float a3 = sQ[dd * PAD + ty * 4 + 3];
            acc[0][0] += a0 * b4.x; acc[0][1] += a0 * b4.y; acc[0][2] += a0 * b4.z; acc[0][3] += a0 * b4.w;
            acc[1][0] += a1 * b4.x; acc[1][1] += a1 * b4.y; acc[1][2] += a1 * b4.z; acc[1][3] += a1 * b4.w;
            acc[2][0] += a2 * b4.x; acc[2][1] += a2 * b4.y; acc[2][2] += a2 * b4.z; acc[2][3] += a2 * b4.w;
            acc[3][0] += a3 * b4.x; acc[3][1] += a3 * b4.y; acc[3][2] += a3 * b4.z; acc[3][3] += a3 * b4.w;
        }

        // Causal mask on the diagonal tile
        if (jt == qt) {
            #pragma unroll
            for (int i = 0; i < 4; ++i)
                #pragma unroll
                for (int j = 0; j < 4; ++j)
                    if (tx * 4 + j > ty * 4 + i) acc[i][j] = -1e30f;
        }

        // Online softmax (rows shared by the 16 tx lanes of a half-warp)
        #pragma unroll
        for (int i = 0; i < 4; ++i) {
            float mx = fmaxf(fmaxf(acc[i][0], acc[i][1]), fmaxf(acc[i][2], acc[i][3]));
            mx = fmaxf(mx, __shfl_xor_sync(0xffffffffu, mx, 1));
            mx = fmaxf(mx, __shfl_xor_sync(0xffffffffu, mx, 2));
            mx = fmaxf(mx, __shfl_xor_sync(0xffffffffu, mx, 4));
            mx = fmaxf(mx, __shfl_xor_sync(0xffffffffu, mx, 8));
            float mnew = fmaxf(mi[i], mx);
            float c = exp2f(mi[i] - mnew);
            float rs = 0.f;
            #pragma unroll
            for (int j = 0; j < 4; ++j) {
                acc[i][j] = exp2f(acc[i][j] - mnew);
                rs += acc[i][j];
            }
            rs += __shfl_xor_sync(0xffffffffu, rs, 1);
            rs += __shfl_xor_sync(0xffffffffu, rs, 2);
            rs += __shfl_xor_sync(0xffffffffu, rs, 4);
            rs += __shfl_xor_sync(0xffffffffu, rs, 8);
            li[i] = li[i] * c + rs;
            mi[i] = mnew;
            o[i][0] *= c; o[i][1] *= c; o[i][2] *= c; o[i][3] *= c;
        }

        // Stage P to SMEM for the P*V GEMM
        #pragma unroll
        for (int i = 0; i < 4; ++i)
            *(float4*)&sP[(ty * 4 + i) * PAD + tx * 4] =
                make_float4(acc[i][0], acc[i][1], acc[i][2], acc[i][3]);
        __syncthreads();

        // O += P V   (contraction over key)
        #pragma unroll 8
        for (int kk = 0; kk < 64; ++kk) {
            float4 b4 = *(float4*)&sV[kk * PAD + tx * 4];
            float a0 = sP[(ty * 4 + 0) * PAD + kk];
            float a1 = sP[(ty * 4 + 1) * PAD + kk];
            float a2 = sP[(ty * 4 + 2) * PAD + kk];
            float a3 = sP[(ty * 4 + 3) * PAD + kk];
            o[0][0] += a0 * b4.x; o[0][1] += a0 * b4.y; o[0][2] += a0 * b4.z; o[0][3] += a0 * b4.w;
            o[1][0] += a1 * b4.x; o[1][1] += a1 * b4.y; o[1][2] += a1 * b4.z; o[1][3] += a1 * b4.w;
            o[2][0] += a2 * b4.x; o[2][1] += a2 * b4.y; o[2][2] += a2 * b4.z; o[2][3] += a2 * b4.w;
            o[3][0] += a3 * b4.x; o[3][1] += a3 * b4.y; o[3][2] += a3 * b4.z; o[3][3] += a3 * b4.w;
        }
    }

    // Normalize + write ctx in [B,S,H*HD]
    #pragma unroll
    for (int i = 0; i < 4; ++i) {
        float inv = 1.0f / li[i];
        int sg = qt * 64 + ty * 4 + i;
        float4 r = make_float4(o[i][0] * inv, o[i][1] * inv, o[i][2] * inv, o[i][3] * inv);
        *(float4*)&g_ctx[(b * SS + sg) * DOUT + h * HD + tx * 4] = r;
    }
}

// ---------------------------------------------------------------------------
// Output projection: ctx[8192,1024] @ Wo[1024,1024] + bo -> d_out
// ---------------------------------------------------------------------------
__global__ __launch_bounds__(256) void out_gemm_kernel(
    const float* __restrict__ Wo,
    const float* __restrict__ bo,
    float* __restrict__ out)
{
    __shared__ float sA[16][65];
    __shared__ float sB[16][64];

    const int tx = threadIdx.x, ty = threadIdx.y;
    const int tid = ty * 16 + tx;
    const int bm = blockIdx.x, bn = blockIdx.y;

    const float* Arow = g_ctx + (bm * 64 + (tid >> 2)) * DOUT + (tid & 3) * 4;
    const float* Brow = Wo + (tid >> 4) * DOUT + bn * 64 + (tid & 15) * 4;

    float acc[4][4] = {};

    for (int kt = 0; kt < DOUT / 16; ++kt) {
        float4 av = *(const float4*)(Arow + kt * 16);
        float4 bv = *(const float4*)(Brow + kt * 16 * DOUT);

        __syncthreads();
        {
            int r = tid >> 2, c4 = (tid & 3) * 4;
            sA[c4 + 0][r] = av.x;
            sA[c4 + 1][r] = av.y;
            sA[c4 + 2][r] = av.z;
            sA[c4 + 3][r] = av.w;
            *(float4*)&sB[tid >> 4][(tid & 15) * 4] = bv;
        }
        __syncthreads();

        #pragma unroll
        for (int k = 0; k < 16; ++k) {
            float4 b4 = *(float4*)&sB[k][tx * 4];
            float a0 = sA[k][ty * 4 + 0];
            float a1 = sA[k][ty * 4 + 1];
            float a2 = sA[k][ty * 4 + 2];
            float a3 = sA[k][ty * 4 + 3];
            acc[0][0] += a0 * b4.x; acc[0][1] += a0 * b4.y; acc[0][2] += a0 * b4.z; acc[0][3] += a0 * b4.w;
            acc[1][0] += a1 * b4.x; acc[1][1] += a1 * b4.y; acc[1][2] += a1 * b4.z; acc[1][3] += a1 * b4.w;
            acc[2][0] += a2 * b4.x; acc[2][1] += a2 * b4.y; acc[2][2] += a2 * b4.z; acc[2][3] += a2 * b4.w;
            acc[3][0] += a3 * b4.x; acc[3][1] += a3 * b4.y; acc[3][2] += a3 * b4.z; acc[3][3] += a3 * b4.w;
        }
    }

    float4 bias = *(const float4*)&bo[bn * 64 + tx * 4];
    #pragma unroll
    for (int i = 0; i < 4; ++i) {
        int mm = bm * 64 + ty * 4 + i;
        float4 r = make_float4(acc[i][0] + bias.x, acc[i][1] + bias.y,
                               acc[i][2] + bias.z, acc[i][3] + bias.w);
        *(float4*)&out[mm * DOUT + bn * 64 + tx * 4] = r;
    }
}

// ---------------------------------------------------------------------------
extern "C" void kernel_launch(void* const* d_in, const int* in_sizes, int n_in,
                              void* d_out, int out_size)
{
    const float* x  = (const float*)d_in[0];
    const float* Wq = (const float*)d_in[1];
    const float* Wk = (const float*)d_in[2];
    const float* Wv = (const float*)d_in[3];
    const float* Wo = (const float*)d_in[4];
    const float* bo = (const float*)d_in[5];
    float* out = (float*)d_out;

    cudaFuncSetAttribute(attn_kernel, cudaFuncAttributeMaxDynamicSharedMemorySize, ATTN_SMEM);

    qkv_gemm_kernel<<<dim3(128, 16, 3), dim3(16, 16)>>>(x, Wq, Wk, Wv);
    attn_kernel<<<dim3(SS / 64, HH, BB), dim3(16, 16), ATTN_SMEM>>>();
    out_gemm_kernel<<<dim3(128, 16), dim3(16, 16)>>>(Wo, bo, out);
}

// round 3
// speedup vs baseline: 1.7314x; 1.7314x over previous
#include <cuda_runtime.h>
#include <cuda_bf16.h>
#include <cstdint>

#define BB   4
#define HH   16
#define SS   2048
#define HD   64
#define DIN  1024
#define DOUT 1024

// ---------------------------------------------------------------------------
// Scratch (__device__ globals; no allocations allowed)
// ---------------------------------------------------------------------------
__device__ float g_q[BB * HH * SS * HD];             // [B,H,S,HD] fp32
__device__ float g_k[BB * HH * SS * HD];
__device__ float g_v[BB * HH * SS * HD];
__device__ __nv_bfloat16 g_xh[BB * SS * DIN];        // x hi/lo bf16 [8192][1024]
__device__ __nv_bfloat16 g_xl[BB * SS * DIN];
__device__ __nv_bfloat16 g_wth[4 * DIN * DOUT];      // W^T hi/lo bf16 [n][k], 4 mats
__device__ __nv_bfloat16 g_wtl[4 * DIN * DOUT];
__device__ __nv_bfloat16 g_cxh[BB * SS * DOUT];      // ctx hi/lo bf16 [8192][1024]
__device__ __nv_bfloat16 g_cxl[BB * SS * DOUT];

// ---------------------------------------------------------------------------
// Helpers
// ---------------------------------------------------------------------------
__device__ __forceinline__ uint32_t smem_u32(const void* p) {
    uint32_t a;
    asm("{ .reg .u64 t; cvta.to.shared.u64 t, %1; cvt.u32.u64 %0, t; }" : "=r"(a) : "l"(p));
    return a;
}
__device__ __forceinline__ uint32_t pack_bf16(float a, float b) {
    __nv_bfloat162 t = __floats2bfloat162_rn(a, b);
    return *(uint32_t*)&t;
}
__device__ __forceinline__ void ldsm4(uint32_t& r0, uint32_t& r1, uint32_t& r2, uint32_t& r3,
                                      uint32_t addr) {
    asm volatile("ldmatrix.sync.aligned.m8n8.x4.shared.b16 {%0,%1,%2,%3}, [%4];"
                 : "=r"(r0), "=r"(r1), "=r"(r2), "=r"(r3) : "r"(addr));
}
__device__ __forceinline__ void mma16816(float* c, const uint32_t* a, const uint32_t* b) {
    asm volatile(
        "mma.sync.aligned.m16n8k16.row.col.f32.bf16.bf16.f32 "
        "{%0,%1,%2,%3}, {%4,%5,%6,%7}, {%8,%9}, {%0,%1,%2,%3};"
        : "+f"(c[0]), "+f"(c[1]), "+f"(c[2]), "+f"(c[3])
        : "r"(a[0]), "r"(a[1]), "r"(a[2]), "r"(a[3]), "r"(b[0]), "r"(b[1]));
}
__device__ __forceinline__ void cp16(uint32_t dst, const void* src) {
    asm volatile("cp.async.cg.shared.global [%0], [%1], 16;" :: "r"(dst), "l"(src));
}
__device__ __forceinline__ void cp_commit() { asm volatile("cp.async.commit_group;" ::: "memory"); }
__device__ __forceinline__ void cp_wait1()  { asm volatile("cp.async.wait_group 1;" ::: "memory"); }
__device__ __forceinline__ void cp_wait0()  { asm volatile("cp.async.wait_group 0;" ::: "memory"); }

// ---------------------------------------------------------------------------
// Conversion kernels (run once per launch; ~30 us total)
// ---------------------------------------------------------------------------
__global__ __launch_bounds__(256) void conv_x_kernel(const float* __restrict__ x)
{
    int i = (blockIdx.x * 256 + threadIdx.x) * 4;
    float4 v = *(const float4*)(x + i);
    __nv_bfloat16 h0 = __float2bfloat16(v.x), h1 = __float2bfloat16(v.y);
    __nv_bfloat16 h2 = __float2bfloat16(v.z), h3 = __float2bfloat16(v.w);
    float l0 = v.x - __bfloat162float(h0), l1 = v.y - __bfloat162float(h1);
    float l2 = v.z - __bfloat162float(h2), l3 = v.w - __bfloat162float(h3);
    *(uint2*)&g_xh[i] = make_uint2(pack_bf16(__bfloat162float(h0), __bfloat162float(h1)),
                                   pack_bf16(__bfloat162float(h2), __bfloat162float(h3)));
    *(uint2*)&g_xl[i] = make_uint2(pack_bf16(l0, l1), pack_bf16(l2, l3));
}

__global__ __launch_bounds__(256) void conv_w_kernel(
    const float* __restrict__ Wq, const float* __restrict__ Wk,
    const float* __restrict__ Wv, const float* __restrict__ Wo)
{
    const int z = blockIdx.z;
    const float* W = (z == 0) ? Wq : (z == 1) ? Wk : (z == 2) ? Wv : Wo;
    __shared__ float t[32][33];
    const int k0 = blockIdx.y * 32, n0 = blockIdx.x * 32;
    const int tx = threadIdx.x, ty = threadIdx.y;   // 32 x 8
    #pragma unroll
    for (int i = 0; i < 4; ++i)
        t[ty + i * 8][tx] = W[(size_t)(k0 + ty + i * 8) * DOUT + n0 + tx];
    __syncthreads();
    __nv_bfloat16* wh = g_wth + (size_t)z * DIN * DOUT;
    __nv_bfloat16* wl = g_wtl + (size_t)z * DIN * DOUT;
    #pragma unroll
    for (int i = 0; i < 4; ++i) {
        int n = n0 + ty + i * 8, k = k0 + tx;
        float v = t[tx][ty + i * 8];                 // = W[k][n]
        __nv_bfloat16 h = __float2bfloat16(v);
        wh[(size_t)n * DIN + k] = h;
        wl[(size_t)n * DIN + k] = __float2bfloat16(v - __bfloat162float(h));
    }
}

// ---------------------------------------------------------------------------
// bf16 hi/lo split GEMM via mma.sync (m16n8k16).  CTA 128x128, K-chunks of 64.
// MODE 0: A = x (hi/lo), B = W^T[z], out -> g_q/g_k/g_v in [B,H,S,HD] fp32.
// MODE 1: A = ctx (hi/lo), B = Wo^T, +bias, out -> d_out fp32.
// ---------------------------------------------------------------------------
#define KC     64
#define PITCH  144                      // bytes per smem row (72 bf16) — conflict-free
#define TILEB  (128 * PITCH)            // 18432
#define STAGEB (4 * TILEB)              // Ah, Al, Bh, Bl
#define GSMEM  (2 * STAGEB)             // 147456

template<int MODE>
__global__ __launch_bounds__(256) void mma_gemm(const float* __restrict__ bias,
                                                float* __restrict__ dout)
{
    extern __shared__ char smc[];
    const uint32_t smb = smem_u32(smc);

    const int tid  = threadIdx.x;
    const int lane = tid & 31;
    const int wid  = tid >> 5;
    const int wm   = (wid & 1) * 64;     // warp m offset in CTA tile
    const int wn   = (wid >> 1) * 32;    // warp n offset

    const int m0 = blockIdx.x * 128;
    const int n0 = blockIdx.y * 128;
    const int bz = (MODE == 0) ? blockIdx.z : 3;

    const __nv_bfloat16* Ah = (MODE == 0) ? g_xh : g_cxh;
    const __nv_bfloat16* Al = (MODE == 0) ? g_xl : g_cxl;
    const __nv_bfloat16* Bh = g_wth + (size_t)bz * DIN * DOUT;
    const __nv_bfloat16* Bl = g_wtl + (size_t)bz * DIN * DOUT;

    const char* agh = (const char*)Ah + ((size_t)m0 * DIN) * 2;
    const char* agl = (const char*)Al + ((size_t)m0 * DIN) * 2;
    const char* bgh = (const char*)Bh + ((size_t)n0 * DIN) * 2;
    const char* bgl = (const char*)Bl + ((size_t)n0 * DIN) * 2;

    // ---- async tile loader: chunk c -> stage st ----
    auto load = [&](int c, int st) {
        const uint32_t base = smb + st * STAGEB;
        const size_t cko = (size_t)c * KC * 2;       // byte offset within a row
        #pragma unroll
        for (int i = 0; i < 4; ++i) {
            int s   = tid + i * 256;                 // 0..1023
            int r   = s >> 3;                        // row 0..127
            int c16 = s & 7;                         // 16B segment
            size_t  go  = (size_t)r * (DIN * 2) + cko + c16 * 16;
            uint32_t dof = r * PITCH + c16 * 16;
            cp16(base + dof,              agh + go);
            cp16(base + TILEB + dof,      agl + go);
            cp16(base + 2 * TILEB + dof,  bgh + go);
            cp16(base + 3 * TILEB + dof,  bgl + go);
        }
    };

    float C[4][4][4] = {};

    // ldmatrix lane address components
    const uint32_t aRow = wm + (lane & 15);
    const uint32_t aCol = (lane >> 4) * 16;                      // bytes
    const uint32_t bRow = wn + ((lane >> 4) << 3) + (lane & 7);
    const uint32_t bCol = ((lane >> 3) & 1) * 16;                // bytes

    load(0, 0);
    cp_commit();

    for (int c = 0; c < DIN / KC; ++c) {
        const int st = c & 1;
        if (c + 1 < DIN / KC) { load(c + 1, st ^ 1); cp_commit(); cp_wait1(); }
        else                  { cp_wait0(); }
        __syncthreads();

        const uint32_t sA = smb + st * STAGEB;
        const uint32_t sB = sA + 2 * TILEB;

        #pragma unroll
        for (int ks = 0; ks < 4; ++ks) {
            uint32_t ah[4][4], al[4][4], bh[4][2], bl[4][2];
            #pragma unroll
            for (int i = 0; i < 4; ++i) {
                uint32_t ad = sA + (aRow + i * 16) * PITCH + ks * 32 + aCol;
                ldsm4(ah[i][0], ah[i][1], ah[i][2], ah[i][3], ad);
                ldsm4(al[i][0], al[i][1], al[i][2], al[i][3], ad + TILEB);
            }
            #pragma unroll
            for (int p = 0; p < 2; ++p) {
                uint32_t bd = sB + (bRow + p * 16) * PITCH + ks * 32 + bCol;
                ldsm4(bh[2*p][0], bh[2*p][1], bh[2*p+1][0], bh[2*p+1][1], bd);
                ldsm4(bl[2*p][0], bl[2*p][1], bl[2*p+1][0], bl[2*p+1][1], bd + TILEB);
            }
            #pragma unroll
            for (int i = 0; i < 4; ++i)
                #pragma unroll
                for (int j = 0; j < 4; ++j) {
                    mma16816(C[i][j], ah[i], bh[j]);
                    mma16816(C[i][j], ah[i], bl[j]);
                    mma16816(C[i][j], al[i], bh[j]);
                }
        }
        __syncthreads();
    }

    // ---- epilogue ----
    const int rr = lane >> 2;            // 0..7
    const int cc = (lane & 3) * 2;       // 0,2,4,6
    #pragma unroll
    for (int i = 0; i < 4; ++i) {
        #pragma unroll
        for (int j = 0; j < 4; ++j) {
            int m1 = m0 + wm + i * 16 + rr;
            int m2 = m1 + 8;
            int n  = n0 + wn + j * 8 + cc;
            if (MODE == 0) {
                float* outp = (bz == 0) ? g_q : (bz == 1) ? g_k : g_v;
                int head = n >> 6, hd = n & 63;
                {
                    int b = m1 >> 11, s = m1 & 2047;
                    *(float2*)&outp[(((size_t)(b * HH + head) * SS + s) * HD) + hd] =
                        make_float2(C[i][j][0], C[i][j][1]);
                }
                {
                    int b = m2 >> 11, s = m2 & 2047;
                    *(float2*)&outp[(((size_t)(b * HH + head) * SS + s) * HD) + hd] =
                        make_float2(C[i][j][2], C[i][j][3]);
                }
            } else {
                float b0 = bias[n], b1 = bias[n + 1];
                *(float2*)&dout[(size_t)m1 * DOUT + n] = make_float2(C[i][j][0] + b0, C[i][j][1] + b1);
                *(float2*)&dout[(size_t)m2 * DOUT + n] = make_float2(C[i][j][2] + b0, C[i][j][3] + b1);
            }
        }
    }
}

// ---------------------------------------------------------------------------
// Causal flash attention, fp32 (unchanged core; writes ctx as bf16 hi/lo).
// ---------------------------------------------------------------------------
#define PAD 68
#define ATTN_SMEM (4 * 64 * PAD * 4)

__global__ __launch_bounds__(256) void attn_kernel()
{
    extern __shared__ float sm[];
    float* sQ = sm;
    float* sK = sm + 64 * PAD;
    float* sV = sm + 2 * 64 * PAD;
    float* sP = sm + 3 * 64 * PAD;

    const int qt = blockIdx.x, h = blockIdx.y, b = blockIdx.z;
    const float* qb = g_q + ((b * HH + h) * SS) * HD;
    const float* kb = g_k + ((b * HH + h) * SS) * HD;
    const float* vb = g_v + ((b * HH + h) * SS) * HD;

    const int tx = threadIdx.x, ty = threadIdx.y;
    const int tid = ty * 16 + tx;
    const float qscale = 0.125f * 1.4426950408889634f;

    for (int off = tid; off < 4096; off += 256) {
        int d = off & 63, s = off >> 6;
        sQ[d * PAD + s] = qb[(qt * 64 + s) * HD + d] * qscale;
    }

    float o[4][4] = {};
    float mi[4] = {-1e30f, -1e30f, -1e30f, -1e30f};
    float li[4] = {};

    for (int jt = 0; jt <= qt; ++jt) {
        __syncthreads();
        for (int off = tid; off < 4096; off += 256) {
            int d = off & 63, s = off >> 6;
            int g = (jt * 64 + s) * HD + d;
            sK[d * PAD + s] = kb[g];
            sV[s * PAD + d] = vb[g];
        }
        __syncthreads();

        float acc[4][4] = {};
        #pragma unroll 8
        for (int dd = 0; dd < 64; ++dd) {
            float4 b4 = *(float4*)&sK[dd * PAD + tx * 4];
            float a0 = sQ[dd * PAD + ty * 4 + 0];
            float a1 = sQ[dd * PAD + ty * 4 + 1];
            float a2 = sQ[dd * PAD + ty * 4 + 2];
            float a3 = sQ[dd * PAD + ty * 4 + 3];
            acc[0][0] += a0 * b4.x; acc[0][1] += a0 * b4.y; acc[0][2] += a0 * b4.z; acc[0][3] += a0 * b4.w;
            acc[1][0] += a1 * b4.x; acc[1][1] += a1 * b4.y; acc[1][2] += a1 * b4.z; acc[1][3] += a1 * b4.w;
            acc[2][0] += a2 * b4.x; acc[2][1] += a2 * b4.y; acc[2][2] += a2 * b4.z; acc[2][3] += a2 * b4.w;
            acc[3][0] += a3 * b4.x; acc[3][1] += a3 * b4.y; acc[3][2] += a3 * b4.z; acc[3][3] += a3 * b4.w;
        }

        if (jt == qt) {
            #pragma unroll
            for (int i = 0; i < 4; ++i)
                #pragma unroll
                for (int j = 0; j < 4; ++j)
                    if (tx * 4 + j > ty * 4 + i) acc[i][j] = -1e30f;
        }

        #pragma unroll
        for (int i = 0; i < 4; ++i) {
            float mx = fmaxf(fmaxf(acc[i][0], acc[i][1]), fmaxf(acc[i][2], acc[i][3]));
            mx = fmaxf(mx, __shfl_xor_sync(0xffffffffu, mx, 1));
            mx = fmaxf(mx, __shfl_xor_sync(0xffffffffu, mx, 2));
            mx = fmaxf(mx, __shfl_xor_sync(0xffffffffu, mx, 4));
            mx = fmaxf(mx, __shfl_xor_sync(0xffffffffu, mx, 8));
            float mnew = fmaxf(mi[i], mx);
            float c = exp2f(mi[i] - mnew);
            float rs = 0.f;
            #pragma unroll
            for (int j = 0; j < 4; ++j) {
                acc[i][j] = exp2f(acc[i][j] - mnew);
                rs += acc[i][j];
            }
            rs += __shfl_xor_sync(0xffffffffu, rs, 1);
            rs += __shfl_xor_sync(0xffffffffu, rs, 2);
            rs += __shfl_xor_sync(0xffffffffu, rs, 4);
            rs += __shfl_xor_sync(0xffffffffu, rs, 8);
            li[i] = li[i] * c + rs;
            mi[i] = mnew;
            o[i][0] *= c; o[i][1] *= c; o[i][2] *= c; o[i][3] *= c;
        }

        #pragma unroll
        for (int i = 0; i < 4; ++i)
            *(float4*)&sP[(ty * 4 + i) * PAD + tx * 4] =
                make_float4(acc[i][0], acc[i][1], acc[i][2], acc[i][3]);
        __syncthreads();

        #pragma unroll 8
        for (int kk = 0; kk < 64; ++kk) {
            float4 b4 = *(float4*)&sV[kk * PAD + tx * 4];
            float a0 = sP[(ty * 4 + 0) * PAD + kk];
            float a1 = sP[(ty * 4 + 1) * PAD + kk];
            float a2 = sP[(ty * 4 + 2) * PAD + kk];
            float a3 = sP[(ty * 4 + 3) * PAD + kk];
            o[0][0] += a0 * b4.x; o[0][1] += a0 * b4.y; o[0][2] += a0 * b4.z; o[0][3] += a0 * b4.w;
            o[1][0] += a1 * b4.x; o[1][1] += a1 * b4.y; o[1][2] += a1 * b4.z; o[1][3] += a1 * b4.w;
            o[2][0] += a2 * b4.x; o[2][1] += a2 * b4.y; o[2][2] += a2 * b4.z; o[2][3] += a2 * b4.w;
            o[3][0] += a3 * b4.x; o[3][1] += a3 * b4.y; o[3][2] += a3 * b4.z; o[3][3] += a3 * b4.w;
        }
    }

    #pragma unroll
    for (int i = 0; i < 4; ++i) {
        float inv = 1.0f / li[i];
        int sg = qt * 64 + ty * 4 + i;
        float v0 = o[i][0] * inv, v1 = o[i][1] * inv, v2 = o[i][2] * inv, v3 = o[i][3] * inv;
        __nv_bfloat16 h0 = __float2bfloat16(v0), h1 = __float2bfloat16(v1);
        __nv_bfloat16 h2 = __float2bfloat16(v2), h3 = __float2bfloat16(v3);
        float l0 = v0 - __bfloat162float(h0), l1 = v1 - __bfloat162float(h1);
        float l2 = v2 - __bfloat162float(h2), l3 = v3 - __bfloat162float(h3);
        size_t idx = (size_t)(b * SS + sg) * DOUT + h * HD + tx * 4;
        *(uint2*)&g_cxh[idx] = make_uint2(pack_bf16(__bfloat162float(h0), __bfloat162float(h1)),
                                          pack_bf16(__bfloat162float(h2), __bfloat162float(h3)));
        *(uint2*)&g_cxl[idx] = make_uint2(pack_bf16(l0, l1), pack_bf16(l2, l3));
    }
}

// ---------------------------------------------------------------------------
extern "C" void kernel_launch(void* const* d_in, const int* in_sizes, int n_in,
                              void* d_out, int out_size)
{
    const float* x  = (const float*)d_in[0];
    const float* Wq = (const float*)d_in[1];
    const float* Wk = (const float*)d_in[2];
    const float* Wv = (const float*)d_in[3];
    const float* Wo = (const float*)d_in[4];
    const float* bo = (const float*)d_in[5];
    float* out = (float*)d_out;

    cudaFuncSetAttribute(mma_gemm<0>, cudaFuncAttributeMaxDynamicSharedMemorySize, GSMEM);
    cudaFuncSetAttribute(mma_gemm<1>, cudaFuncAttributeMaxDynamicSharedMemorySize, GSMEM);
    cudaFuncSetAttribute(attn_kernel, cudaFuncAttributeMaxDynamicSharedMemorySize, ATTN_SMEM);

    conv_x_kernel<<<BB * SS * DIN / 1024, 256>>>(x);
    conv_w_kernel<<<dim3(32, 32, 4), dim3(32, 8)>>>(Wq, Wk, Wv, Wo);
    mma_gemm<0><<<dim3(64, 8, 3), 256, GSMEM>>>(nullptr, nullptr);
    attn_kernel<<<dim3(SS / 64, HH, BB), dim3(16, 16), ATTN_SMEM>>>();
    mma_gemm<1><<<dim3(64, 8), 256, GSMEM>>>(bo, out);
}

// round 4
// speedup vs baseline: 3.0742x; 1.7756x over previous
#include <cuda_runtime.h>
#include <cuda_bf16.h>
#include <cstdint>

#define BB   4
#define HH   16
#define SS   2048
#define HD   64
#define DIN  1024
#define DOUT 1024

// ---------------------------------------------------------------------------
// Scratch (__device__ globals; no allocations allowed)
// ---------------------------------------------------------------------------
__device__ __nv_bfloat16 g_xh[BB * SS * DIN];        // x hi/lo bf16
__device__ __nv_bfloat16 g_xl[BB * SS * DIN];
__device__ __nv_bfloat16 g_wth[4 * DIN * DOUT];      // W^T hi/lo bf16 [n][k]
__device__ __nv_bfloat16 g_wtl[4 * DIN * DOUT];
__device__ __nv_bfloat16 g_qh[BB * HH * SS * HD];    // Q (pre-scaled) hi/lo [B,H,S,HD]
__device__ __nv_bfloat16 g_ql[BB * HH * SS * HD];
__device__ __nv_bfloat16 g_kh[BB * HH * SS * HD];
__device__ __nv_bfloat16 g_kl[BB * HH * SS * HD];
__device__ __nv_bfloat16 g_vh[BB * HH * SS * HD];
__device__ __nv_bfloat16 g_vl[BB * HH * SS * HD];
__device__ __nv_bfloat16 g_cxh[BB * SS * DOUT];      // ctx hi/lo [8192][1024]
__device__ __nv_bfloat16 g_cxl[BB * SS * DOUT];

// ---------------------------------------------------------------------------
// Helpers
// ---------------------------------------------------------------------------
__device__ __forceinline__ uint32_t smem_u32(const void* p) {
    uint32_t a;
    asm("{ .reg .u64 t; cvta.to.shared.u64 t, %1; cvt.u32.u64 %0, t; }" : "=r"(a) : "l"(p));
    return a;
}
__device__ __forceinline__ uint32_t pack_bf16(float a, float b) {
    __nv_bfloat162 t = __floats2bfloat162_rn(a, b);
    return *(uint32_t*)&t;
}
__device__ __forceinline__ uint32_t pack2h(__nv_bfloat16 x, __nv_bfloat16 y) {
    __nv_bfloat162 t; t.x = x; t.y = y;
    return *(uint32_t*)&t;
}
__device__ __forceinline__ void ldsm4(uint32_t& r0, uint32_t& r1, uint32_t& r2, uint32_t& r3,
                                      uint32_t addr) {
    asm volatile("ldmatrix.sync.aligned.m8n8.x4.shared.b16 {%0,%1,%2,%3}, [%4];"
                 : "=r"(r0), "=r"(r1), "=r"(r2), "=r"(r3) : "r"(addr));
}
__device__ __forceinline__ void ldsm4t(uint32_t& r0, uint32_t& r1, uint32_t& r2, uint32_t& r3,
                                       uint32_t addr) {
    asm volatile("ldmatrix.sync.aligned.m8n8.x4.trans.shared.b16 {%0,%1,%2,%3}, [%4];"
                 : "=r"(r0), "=r"(r1), "=r"(r2), "=r"(r3) : "r"(addr));
}
__device__ __forceinline__ void mma16816(float* c, const uint32_t* a, const uint32_t* b) {
    asm volatile(
        "mma.sync.aligned.m16n8k16.row.col.f32.bf16.bf16.f32 "
        "{%0,%1,%2,%3}, {%4,%5,%6,%7}, {%8,%9}, {%0,%1,%2,%3};"
        : "+f"(c[0]), "+f"(c[1]), "+f"(c[2]), "+f"(c[3])
        : "r"(a[0]), "r"(a[1]), "r"(a[2]), "r"(a[3]), "r"(b[0]), "r"(b[1]));
}
__device__ __forceinline__ void cp16(uint32_t dst, const void* src) {
    asm volatile("cp.async.cg.shared.global [%0], [%1], 16;" :: "r"(dst), "l"(src));
}
__device__ __forceinline__ void cp_commit() { asm volatile("cp.async.commit_group;" ::: "memory"); }
__device__ __forceinline__ void cp_wait1()  { asm volatile("cp.async.wait_group 1;" ::: "memory"); }
__device__ __forceinline__ void cp_wait0()  { asm volatile("cp.async.wait_group 0;" ::: "memory"); }

// ---------------------------------------------------------------------------
// Conversion kernels
// ---------------------------------------------------------------------------
__global__ __launch_bounds__(256) void conv_x_kernel(const float* __restrict__ x)
{
    int i = (blockIdx.x * 256 + threadIdx.x) * 4;
    float4 v = *(const float4*)(x + i);
    __nv_bfloat16 h0 = __float2bfloat16(v.x), h1 = __float2bfloat16(v.y);
    __nv_bfloat16 h2 = __float2bfloat16(v.z), h3 = __float2bfloat16(v.w);
    float l0 = v.x - __bfloat162float(h0), l1 = v.y - __bfloat162float(h1);
    float l2 = v.z - __bfloat162float(h2), l3 = v.w - __bfloat162float(h3);
    *(uint2*)&g_xh[i] = make_uint2(pack2h(h0, h1), pack2h(h2, h3));
    *(uint2*)&g_xl[i] = make_uint2(pack_bf16(l0, l1), pack_bf16(l2, l3));
}

__global__ __launch_bounds__(256) void conv_w_kernel(
    const float* __restrict__ Wq, const float* __restrict__ Wk,
    const float* __restrict__ Wv, const float* __restrict__ Wo)
{
    const int z = blockIdx.z;
    const float* W = (z == 0) ? Wq : (z == 1) ? Wk : (z == 2) ? Wv : Wo;
    __shared__ float t[32][33];
    const int k0 = blockIdx.y * 32, n0 = blockIdx.x * 32;
    const int tx = threadIdx.x, ty = threadIdx.y;   // 32 x 8
    #pragma unroll
    for (int i = 0; i < 4; ++i)
        t[ty + i * 8][tx] = W[(size_t)(k0 + ty + i * 8) * DOUT + n0 + tx];
    __syncthreads();
    __nv_bfloat16* wh = g_wth + (size_t)z * DIN * DOUT;
    __nv_bfloat16* wl = g_wtl + (size_t)z * DIN * DOUT;
    #pragma unroll
    for (int i = 0; i < 4; ++i) {
        int n = n0 + ty + i * 8, k = k0 + tx;
        float v = t[tx][ty + i * 8];                 // = W[k][n]
        __nv_bfloat16 h = __float2bfloat16(v);
        wh[(size_t)n * DIN + k] = h;
        wl[(size_t)n * DIN + k] = __float2bfloat16(v - __bfloat162float(h));
    }
}

// ---------------------------------------------------------------------------
// bf16 hi/lo split GEMM via mma.sync.  CTA 128x128, K-chunks of 64.
// MODE 0: A = x, B = W^T[z] -> Q/K/V as bf16 hi/lo [B,H,S,HD] (Q pre-scaled).
// MODE 1: A = ctx, B = Wo^T, +bias -> d_out fp32.
// ---------------------------------------------------------------------------
#define KC     64
#define PITCH  144
#define TILEB  (128 * PITCH)
#define STAGEB (4 * TILEB)
#define GSMEM  (2 * STAGEB)

template<int MODE>
__global__ __launch_bounds__(256) void mma_gemm(const float* __restrict__ bias,
                                                float* __restrict__ dout)
{
    extern __shared__ char smc[];
    const uint32_t smb = smem_u32(smc);

    const int tid  = threadIdx.x;
    const int lane = tid & 31;
    const int wid  = tid >> 5;
    const int wm   = (wid & 1) * 64;
    const int wn   = (wid >> 1) * 32;

    const int m0 = blockIdx.x * 128;
    const int n0 = blockIdx.y * 128;
    const int bz = (MODE == 0) ? blockIdx.z : 3;

    const __nv_bfloat16* Ah = (MODE == 0) ? g_xh : g_cxh;
    const __nv_bfloat16* Al = (MODE == 0) ? g_xl : g_cxl;
    const __nv_bfloat16* Bh = g_wth + (size_t)bz * DIN * DOUT;
    const __nv_bfloat16* Bl = g_wtl + (size_t)bz * DIN * DOUT;

    const char* agh = (const char*)Ah + ((size_t)m0 * DIN) * 2;
    const char* agl = (const char*)Al + ((size_t)m0 * DIN) * 2;
    const char* bgh = (const char*)Bh + ((size_t)n0 * DIN) * 2;
    const char* bgl = (const char*)Bl + ((size_t)n0 * DIN) * 2;

    auto load = [&](int c, int st) {
        const uint32_t base = smb + st * STAGEB;
        const size_t cko = (size_t)c * KC * 2;
        #pragma unroll
        for (int i = 0; i < 4; ++i) {
            int s   = tid + i * 256;
            int r   = s >> 3;
            int c16 = s & 7;
            size_t  go  = (size_t)r * (DIN * 2) + cko + c16 * 16;
            uint32_t dof = r * PITCH + c16 * 16;
            cp16(base + dof,              agh + go);
            cp16(base + TILEB + dof,      agl + go);
            cp16(base + 2 * TILEB + dof,  bgh + go);
            cp16(base + 3 * TILEB + dof,  bgl + go);
        }
    };

    float C[4][4][4] = {};

    const uint32_t aRow = wm + (lane & 15);
    const uint32_t aCol = (lane >> 4) * 16;
    const uint32_t bRow = wn + ((lane >> 4) << 3) + (lane & 7);
    const uint32_t bCol = ((lane >> 3) & 1) * 16;

    load(0, 0);
    cp_commit();

    for (int c = 0; c < DIN / KC; ++c) {
        const int st = c & 1;
        if (c + 1 < DIN / KC) { load(c + 1, st ^ 1); cp_commit(); cp_wait1(); }
        else                  { cp_wait0(); }
        __syncthreads();

        const uint32_t sA = smb + st * STAGEB;
        const uint32_t sB = sA + 2 * TILEB;

        #pragma unroll
        for (int ks = 0; ks < 4; ++ks) {
            uint32_t ah[4][4], al[4][4], bh[4][2], bl[4][2];
            #pragma unroll
            for (int i = 0; i < 4; ++i) {
                uint32_t ad = sA + (aRow + i * 16) * PITCH + ks * 32 + aCol;
                ldsm4(ah[i][0], ah[i][1], ah[i][2], ah[i][3], ad);
                ldsm4(al[i][0], al[i][1], al[i][2], al[i][3], ad + TILEB);
            }
            #pragma unroll
            for (int p = 0; p < 2; ++p) {
                uint32_t bd = sB + (bRow + p * 16) * PITCH + ks * 32 + bCol;
                ldsm4(bh[2*p][0], bh[2*p][1], bh[2*p+1][0], bh[2*p+1][1], bd);
                ldsm4(bl[2*p][0], bl[2*p][1], bl[2*p+1][0], bl[2*p+1][1], bd + TILEB);
            }
            #pragma unroll
            for (int i = 0; i < 4; ++i)
                #pragma unroll
                for (int j = 0; j < 4; ++j) {
                    mma16816(C[i][j], ah[i], bh[j]);
                    mma16816(C[i][j], ah[i], bl[j]);
                    mma16816(C[i][j], al[i], bh[j]);
                }
        }
        __syncthreads();
    }

    // ---- epilogue ----
    const int rr = lane >> 2;
    const int cc = (lane & 3) * 2;
    const float scl = (MODE == 0 && bz == 0) ? 0.1803368801111244f : 1.0f; // (1/8)*log2(e)
    #pragma unroll
    for (int i = 0; i < 4; ++i) {
        #pragma unroll
        for (int j = 0; j < 4; ++j) {
            int m1 = m0 + wm + i * 16 + rr;
            int m2 = m1 + 8;
            int n  = n0 + wn + j * 8 + cc;
            if (MODE == 0) {
                __nv_bfloat16* oh = (bz == 0) ? g_qh : (bz == 1) ? g_kh : g_vh;
                __nv_bfloat16* ol = (bz == 0) ? g_ql : (bz == 1) ? g_kl : g_vl;
                int head = n >> 6, hd = n & 63;
                #pragma unroll
                for (int half = 0; half < 2; ++half) {
                    int mm = half ? m2 : m1;
                    float v0 = C[i][j][half * 2] * scl, v1 = C[i][j][half * 2 + 1] * scl;
                    __nv_bfloat16 h0 = __float2bfloat16(v0), h1 = __float2bfloat16(v1);
                    float l0 = v0 - __bfloat162float(h0), l1 = v1 - __bfloat162float(h1);
                    int b = mm >> 11, s = mm & 2047;
                    size_t idx = (((size_t)(b * HH + head) * SS + s) * HD) + hd;
                    *(uint32_t*)&oh[idx] = pack2h(h0, h1);
                    *(uint32_t*)&ol[idx] = pack_bf16(l0, l1);
                }
            } else {
                float b0 = bias[n], b1 = bias[n + 1];
                *(float2*)&dout[(size_t)m1 * DOUT + n] = make_float2(C[i][j][0] + b0, C[i][j][1] + b1);
                *(float2*)&dout[(size_t)m2 * DOUT + n] = make_float2(C[i][j][2] + b0, C[i][j][3] + b1);
            }
        }
    }
}

// ---------------------------------------------------------------------------
// Tensor-core causal flash attention (bf16 hi/lo split, mma.sync).
// CTA: 128 queries x (b,h).  8 warps x 16 rows.  Key tiles of 64, cp.async x2.
// ---------------------------------------------------------------------------
#define APITCH  144
#define QBYTES  (128 * APITCH)       // 18432
#define KVBYTES (64 * APITCH)        // 9216
#define OFF_ST  (2 * QBYTES)         // 36864
#define STG_B   (4 * KVBYTES)        // 36864
#define ATTN_SMEM (OFF_ST + 2 * STG_B)  // 110592

__global__ __launch_bounds__(256, 1) void attn_mma_kernel()
{
    extern __shared__ char smc[];
    const uint32_t smb = smem_u32(smc);

    const int tid  = threadIdx.x;
    const int lane = tid & 31;
    const int wid  = tid >> 5;
    const int qt   = (int)(gridDim.x - 1) - (int)blockIdx.x;  // heavy tiles first
    const int h    = blockIdx.y, b = blockIdx.z;
    const int wq   = wid * 16;

    const size_t bh = ((size_t)(b * HH + h)) * SS;
    const char* gqh = (const char*)(g_qh + (bh + (size_t)qt * 128) * HD);
    const char* gql = (const char*)(g_ql + (bh + (size_t)qt * 128) * HD);
    const char* gkh = (const char*)(g_kh + bh * HD);
    const char* gkl = (const char*)(g_kl + bh * HD);
    const char* gvh = (const char*)(g_vh + bh * HD);
    const char* gvl = (const char*)(g_vl + bh * HD);

    // Q tile (128 rows x 128B) hi/lo
    #pragma unroll
    for (int i = 0; i < 4; ++i) {
        int s = tid + i * 256;                 // 0..1023
        int r = s >> 3, seg = s & 7;
        uint32_t doff = r * APITCH + seg * 16;
        size_t   goff = (size_t)r * 128 + seg * 16;
        cp16(smb + doff,          gqh + goff);
        cp16(smb + QBYTES + doff, gql + goff);
    }
    auto loadKV = [&](int jt, int st) {
        const uint32_t base = smb + OFF_ST + st * STG_B;
        const size_t g0 = (size_t)jt * 64 * 128;
        #pragma unroll
        for (int i = 0; i < 2; ++i) {
            int s = tid + i * 256;             // 0..511
            int r = s >> 3, seg = s & 7;
            uint32_t doff = r * APITCH + seg * 16;
            size_t   goff = g0 + (size_t)r * 128 + seg * 16;
            cp16(base + doff,               gkh + goff);
            cp16(base + KVBYTES + doff,     gkl + goff);
            cp16(base + 2 * KVBYTES + doff, gvh + goff);
            cp16(base + 3 * KVBYTES + doff, gvl + goff);
        }
    };
    loadKV(0, 0);
    cp_commit();

    uint32_t qh[4][4], ql[4][4];
    float O[8][4] = {};
    float m0 = -1e30f, m1 = -1e30f, l0 = 0.f, l1 = 0.f;

    const uint32_t aoff = (wq + (lane & 15)) * APITCH + (lane >> 4) * 16;
    const uint32_t krow = (((lane >> 4) << 3) + (lane & 7)) * APITCH + ((lane >> 3) & 1) * 16;
    const uint32_t vrow = (lane & 15) * APITCH + (lane >> 4) * 16;

    const int jmax = 2 * qt + 1;
    for (int jt = 0; jt <= jmax; ++jt) {
        const int st = jt & 1;
        if (jt < jmax) { loadKV(jt + 1, st ^ 1); cp_commit(); cp_wait1(); }
        else           { cp_wait0(); }
        __syncthreads();

        if (jt == 0) {
            #pragma unroll
            for (int f = 0; f < 4; ++f) {
                ldsm4(qh[f][0], qh[f][1], qh[f][2], qh[f][3], smb + aoff + f * 32);
                ldsm4(ql[f][0], ql[f][1], ql[f][2], ql[f][3], smb + QBYTES + aoff + f * 32);
            }
        }

        const bool active = !(jt == jmax && wid < 4);   // warps 0-3: last tile fully masked
        if (active) {
            const uint32_t kb = smb + OFF_ST + st * STG_B;

            // ---- S = Q K^T (hi/lo 3-MMA split) ----
            float s_[8][4] = {};
            #pragma unroll
            for (int jp = 0; jp < 4; ++jp) {
                #pragma unroll
                for (int f = 0; f < 4; ++f) {
                    uint32_t a = kb + krow + jp * 16 * APITCH + f * 32;
                    uint32_t kh[4], kl[4];
                    ldsm4(kh[0], kh[1], kh[2], kh[3], a);
                    ldsm4(kl[0], kl[1], kl[2], kl[3], a + KVBYTES);
                    mma16816(s_[2*jp],     qh[f], kh);
                    mma16816(s_[2*jp],     ql[f], kh);
                    mma16816(s_[2*jp],     qh[f], kl);
                    mma16816(s_[2*jp + 1], qh[f], kh + 2);
                    mma16816(s_[2*jp + 1], ql[f], kh + 2);
                    mma16816(s_[2*jp + 1], qh[f], kl + 2);
                }
            }

            // ---- causal mask (diagonal tiles only) ----
            if (jt >= 2 * qt) {
                const int qrow  = qt * 128 + wq + (lane >> 2);
                const int kcol0 = jt * 64 + (lane & 3) * 2;
                #pragma unroll
                for (int j = 0; j < 8; ++j) {
                    int c0 = kcol0 + j * 8, c1 = c0 + 1;
                    if (c0 > qrow)     s_[j][0] = -1e30f;
                    if (c1 > qrow)     s_[j][1] = -1e30f;
                    if (c0 > qrow + 8) s_[j][2] = -1e30f;
                    if (c1 > qrow + 8) s_[j][3] = -1e30f;
                }
            }

            // ---- online softmax (base-2; scale folded into Q) ----
            float mx0 = -1e30f, mx1 = -1e30f;
            #pragma unroll
            for (int j = 0; j < 8; ++j) {
                mx0 = fmaxf(mx0, fmaxf(s_[j][0], s_[j][1]));
                mx1 = fmaxf(mx1, fmaxf(s_[j][2], s_[j][3]));
            }
            mx0 = fmaxf(mx0, __shfl_xor_sync(0xffffffffu, mx0, 1));
            mx0 = fmaxf(mx0, __shfl_xor_sync(0xffffffffu, mx0, 2));
            mx1 = fmaxf(mx1, __shfl_xor_sync(0xffffffffu, mx1, 1));
            mx1 = fmaxf(mx1, __shfl_xor_sync(0xffffffffu, mx1, 2));
            float mn0 = fmaxf(m0, mx0), mn1 = fmaxf(m1, mx1);
            float c0 = exp2f(m0 - mn0), c1 = exp2f(m1 - mn1);
            m0 = mn0; m1 = mn1;
            float rs0 = 0.f, rs1 = 0.f;
            #pragma unroll
            for (int j = 0; j < 8; ++j) {
                s_[j][0] = exp2f(s_[j][0] - mn0);
                s_[j][1] = exp2f(s_[j][1] - mn0);
                s_[j][2] = exp2f(s_[j][2] - mn1);
                s_[j][3] = exp2f(s_[j][3] - mn1);
                rs0 += s_[j][0] + s_[j][1];
                rs1 += s_[j][2] + s_[j][3];
            }
            l0 = l0 * c0 + rs0;
            l1 = l1 * c1 + rs1;
            #pragma unroll
            for (int dj = 0; dj < 8; ++dj) {
                O[dj][0] *= c0; O[dj][1] *= c0;
                O[dj][2] *= c1; O[dj][3] *= c1;
            }

            // ---- O += P V (P from registers via C->A identity; hi/lo split) ----
            const uint32_t vb = kb + 2 * KVBYTES + vrow;
            #pragma unroll
            for (int f = 0; f < 4; ++f) {
                uint32_t ph[4], pl[4];
                #pragma unroll
                for (int t = 0; t < 2; ++t) {
                    float p0 = s_[2*f + t][0], p1 = s_[2*f + t][1];
                    float p2 = s_[2*f + t][2], p3 = s_[2*f + t][3];
                    __nv_bfloat16 h0 = __float2bfloat16(p0), h1 = __float2bfloat16(p1);
                    __nv_bfloat16 h2 = __float2bfloat16(p2), h3 = __float2bfloat16(p3);
                    ph[2*t]   = pack2h(h0, h1);
                    ph[2*t+1] = pack2h(h2, h3);
                    pl[2*t]   = pack_bf16(p0 - __bfloat162float(h0), p1 - __bfloat162float(h1));
                    pl[2*t+1] = pack_bf16(p2 - __bfloat162float(h2), p3 - __bfloat162float(h3));
                }
                const uint32_t va = vb + f * 16 * APITCH;
                #pragma unroll
                for (int dj = 0; dj < 4; ++dj) {
                    uint32_t vh[4], vl[4];
                    ldsm4t(vh[0], vh[1], vh[2], vh[3], va + dj * 32);
                    ldsm4t(vl[0], vl[1], vl[2], vl[3], va + dj * 32 + KVBYTES);
                    mma16816(O[2*dj],     ph, vh);
                    mma16816(O[2*dj],     pl, vh);
                    mma16816(O[2*dj],     ph, vl);
                    mma16816(O[2*dj + 1], ph, vh + 2);
                    mma16816(O[2*dj + 1], pl, vh + 2);
                    mma16816(O[2*dj + 1], ph, vl + 2);
                }
            }
        }
        __syncthreads();
    }

    // ---- finalize: reduce l over quad, normalize, write ctx hi/lo ----
    l0 += __shfl_xor_sync(0xffffffffu, l0, 1);
    l0 += __shfl_xor_sync(0xffffffffu, l0, 2);
    l1 += __shfl_xor_sync(0xffffffffu, l1, 1);
    l1 += __shfl_xor_sync(0xffffffffu, l1, 2);
    const float inv0 = 1.0f / l0, inv1 = 1.0f / l1;

    const int r    = lane >> 2;
    const int dcol = (lane & 3) * 2;
    const int row0 = qt * 128 + wq + r;
    const size_t base0 = ((size_t)b * SS + row0) * DOUT + h * 64;
    const size_t base1 = base0 + (size_t)8 * DOUT;
    #pragma unroll
    for (int dj = 0; dj < 8; ++dj) {
        int d = dj * 8 + dcol;
        {
            float v0 = O[dj][0] * inv0, v1 = O[dj][1] * inv0;
            __nv_bfloat16 h0 = __float2bfloat16(v0), h1 = __float2bfloat16(v1);
            *(uint32_t*)&g_cxh[base0 + d] = pack2h(h0, h1);
            *(uint32_t*)&g_cxl[base0 + d] =
                pack_bf16(v0 - __bfloat162float(h0), v1 - __bfloat162float(h1));
        }
        {
            float v2 = O[dj][2] * inv1, v3 = O[dj][3] * inv1;
            __nv_bfloat16 h2 = __float2bfloat16(v2), h3 = __float2bfloat16(v3);
            *(uint32_t*)&g_cxh[base1 + d] = pack2h(h2, h3);
            *(uint32_t*)&g_cxl[base1 + d] =
                pack_bf16(v2 - __bfloat162float(h2), v3 - __bfloat162float(h3));
        }
    }
}

// ---------------------------------------------------------------------------
extern "C" void kernel_launch(void* const* d_in, const int* in_sizes, int n_in,
                              void* d_out, int out_size)
{
    const float* x  = (const float*)d_in[0];
    const float* Wq = (const float*)d_in[1];
    const float* Wk = (const float*)d_in[2];
    const float* Wv = (const float*)d_in[3];
    const float* Wo = (const float*)d_in[4];
    const float* bo = (const float*)d_in[5];
    float* out = (float*)d_out;

    cudaFuncSetAttribute(mma_gemm<0>, cudaFuncAttributeMaxDynamicSharedMemorySize, GSMEM);
    cudaFuncSetAttribute(mma_gemm<1>, cudaFuncAttributeMaxDynamicSharedMemorySize, GSMEM);
    cudaFuncSetAttribute(attn_mma_kernel, cudaFuncAttributeMaxDynamicSharedMemorySize, ATTN_SMEM);

    conv_x_kernel<<<BB * SS * DIN / 1024, 256>>>(x);
    conv_w_kernel<<<dim3(32, 32, 4), dim3(32, 8)>>>(Wq, Wk, Wv, Wo);
    mma_gemm<0><<<dim3(64, 8, 3), 256, GSMEM>>>(nullptr, nullptr);
    attn_mma_kernel<<<dim3(16, HH, BB), 256, ATTN_SMEM>>>();
    mma_gemm<1><<<dim3(64, 8), 256, GSMEM>>>(bo, out);
}

// round 5
// speedup vs baseline: 3.3321x; 1.0839x over previous
#include <cuda_runtime.h>
#include <cuda_bf16.h>
#include <cstdint>

#define BB   4
#define HH   16
#define SS   2048
#define HD   64
#define DIN  1024
#define DOUT 1024

// ---------------------------------------------------------------------------
// Scratch (__device__ globals; no allocations allowed)
// ---------------------------------------------------------------------------
__device__ __nv_bfloat16 g_xh[BB * SS * DIN];        // x hi/lo bf16
__device__ __nv_bfloat16 g_xl[BB * SS * DIN];
__device__ __nv_bfloat16 g_wth[4 * DIN * DOUT];      // W^T hi/lo bf16 [n][k]
__device__ __nv_bfloat16 g_wtl[4 * DIN * DOUT];
__device__ __nv_bfloat16 g_qh[BB * HH * SS * HD];    // Q (pre-scaled) hi/lo [B,H,S,HD]
__device__ __nv_bfloat16 g_ql[BB * HH * SS * HD];
__device__ __nv_bfloat16 g_kh[BB * HH * SS * HD];
__device__ __nv_bfloat16 g_kl[BB * HH * SS * HD];
__device__ __nv_bfloat16 g_vh[BB * HH * SS * HD];
__device__ __nv_bfloat16 g_vl[BB * HH * SS * HD];
__device__ __nv_bfloat16 g_cxh[BB * SS * DOUT];      // ctx hi/lo [8192][1024]
__device__ __nv_bfloat16 g_cxl[BB * SS * DOUT];

// ---------------------------------------------------------------------------
// Helpers
// ---------------------------------------------------------------------------
__device__ __forceinline__ uint32_t smem_u32(const void* p) {
    uint32_t a;
    asm("{ .reg .u64 t; cvta.to.shared.u64 t, %1; cvt.u32.u64 %0, t; }" : "=r"(a) : "l"(p));
    return a;
}
__device__ __forceinline__ uint32_t pack_bf16(float a, float b) {
    __nv_bfloat162 t = __floats2bfloat162_rn(a, b);
    return *(uint32_t*)&t;
}
__device__ __forceinline__ uint32_t pack2h(__nv_bfloat16 x, __nv_bfloat16 y) {
    __nv_bfloat162 t; t.x = x; t.y = y;
    return *(uint32_t*)&t;
}
__device__ __forceinline__ void ldsm4(uint32_t& r0, uint32_t& r1, uint32_t& r2, uint32_t& r3,
                                      uint32_t addr) {
    asm volatile("ldmatrix.sync.aligned.m8n8.x4.shared.b16 {%0,%1,%2,%3}, [%4];"
                 : "=r"(r0), "=r"(r1), "=r"(r2), "=r"(r3) : "r"(addr));
}
__device__ __forceinline__ void ldsm4t(uint32_t& r0, uint32_t& r1, uint32_t& r2, uint32_t& r3,
                                       uint32_t addr) {
    asm volatile("ldmatrix.sync.aligned.m8n8.x4.trans.shared.b16 {%0,%1,%2,%3}, [%4];"
                 : "=r"(r0), "=r"(r1), "=r"(r2), "=r"(r3) : "r"(addr));
}
__device__ __forceinline__ void mma16816(float* c, const uint32_t* a, const uint32_t* b) {
    asm volatile(
        "mma.sync.aligned.m16n8k16.row.col.f32.bf16.bf16.f32 "
        "{%0,%1,%2,%3}, {%4,%5,%6,%7}, {%8,%9}, {%0,%1,%2,%3};"
        : "+f"(c[0]), "+f"(c[1]), "+f"(c[2]), "+f"(c[3])
        : "r"(a[0]), "r"(a[1]), "r"(a[2]), "r"(a[3]), "r"(b[0]), "r"(b[1]));
}
__device__ __forceinline__ void cp16(uint32_t dst, const void* src) {
    asm volatile("cp.async.cg.shared.global [%0], [%1], 16;" :: "r"(dst), "l"(src));
}
__device__ __forceinline__ void cp_commit() { asm volatile("cp.async.commit_group;" ::: "memory"); }
__device__ __forceinline__ void cp_wait1()  { asm volatile("cp.async.wait_group 1;" ::: "memory"); }
__device__ __forceinline__ void cp_wait0()  { asm volatile("cp.async.wait_group 0;" ::: "memory"); }

// ---------------------------------------------------------------------------
// Conversion kernels
// ---------------------------------------------------------------------------
__global__ __launch_bounds__(256) void conv_x_kernel(const float* __restrict__ x)
{
    int i = (blockIdx.x * 256 + threadIdx.x) * 4;
    float4 v = *(const float4*)(x + i);
    __nv_bfloat16 h0 = __float2bfloat16(v.x), h1 = __float2bfloat16(v.y);
    __nv_bfloat16 h2 = __float2bfloat16(v.z), h3 = __float2bfloat16(v.w);
    float l0 = v.x - __bfloat162float(h0), l1 = v.y - __bfloat162float(h1);
    float l2 = v.z - __bfloat162float(h2), l3 = v.w - __bfloat162float(h3);
    *(uint2*)&g_xh[i] = make_uint2(pack2h(h0, h1), pack2h(h2, h3));
    *(uint2*)&g_xl[i] = make_uint2(pack_bf16(l0, l1), pack_bf16(l2, l3));
}

__global__ __launch_bounds__(256) void conv_w_kernel(
    const float* __restrict__ Wq, const float* __restrict__ Wk,
    const float* __restrict__ Wv, const float* __restrict__ Wo)
{
    const int z = blockIdx.z;
    const float* W = (z == 0) ? Wq : (z == 1) ? Wk : (z == 2) ? Wv : Wo;
    __shared__ float t[32][33];
    const int k0 = blockIdx.y * 32, n0 = blockIdx.x * 32;
    const int tx = threadIdx.x, ty = threadIdx.y;   // 32 x 8
    #pragma unroll
    for (int i = 0; i < 4; ++i)
        t[ty + i * 8][tx] = W[(size_t)(k0 + ty + i * 8) * DOUT + n0 + tx];
    __syncthreads();
    __nv_bfloat16* wh = g_wth + (size_t)z * DIN * DOUT;
    __nv_bfloat16* wl = g_wtl + (size_t)z * DIN * DOUT;
    #pragma unroll
    for (int i = 0; i < 4; ++i) {
        int n = n0 + ty + i * 8, k = k0 + tx;
        float v = t[tx][ty + i * 8];                 // = W[k][n]
        __nv_bfloat16 h = __float2bfloat16(v);
        wh[(size_t)n * DIN + k] = h;
        wl[(size_t)n * DIN + k] = __float2bfloat16(v - __bfloat162float(h));
    }
}

// ---------------------------------------------------------------------------
// bf16 hi/lo split GEMM via mma.sync.  CTA 128x128, 128 threads (warp 64x64),
// K-chunks of 32, 2 stages, 2 CTAs/SM.
// MODE 0: A = x, B = W^T[z] -> Q/K/V as bf16 hi/lo [B,H,S,HD] (Q pre-scaled).
// MODE 1: A = ctx, B = Wo^T, +bias -> d_out fp32.
// ---------------------------------------------------------------------------
#define KC     32
#define PITCH  80                        // 64B row + 16B pad (conflict-free)
#define TILEB  (128 * PITCH)             // 10240
#define STAGEB (4 * TILEB)               // 40960  (Ah, Al, Bh, Bl)
#define GSMEM  (2 * STAGEB)              // 81920  -> 2 CTAs/SM

template<int MODE>
__global__ __launch_bounds__(128, 2) void mma_gemm(const float* __restrict__ bias,
                                                   float* __restrict__ dout)
{
    extern __shared__ char smc[];
    const uint32_t smb = smem_u32(smc);

    const int tid  = threadIdx.x;
    const int lane = tid & 31;
    const int wid  = tid >> 5;
    const int wm   = (wid & 1) * 64;
    const int wn   = (wid >> 1) * 64;

    const int m0 = blockIdx.x * 128;
    const int n0 = blockIdx.y * 128;
    const int bz = (MODE == 0) ? blockIdx.z : 3;

    const __nv_bfloat16* Ah = (MODE == 0) ? g_xh : g_cxh;
    const __nv_bfloat16* Al = (MODE == 0) ? g_xl : g_cxl;
    const __nv_bfloat16* Bh = g_wth + (size_t)bz * DIN * DOUT;
    const __nv_bfloat16* Bl = g_wtl + (size_t)bz * DIN * DOUT;

    const char* agh = (const char*)Ah + ((size_t)m0 * DIN) * 2;
    const char* agl = (const char*)Al + ((size_t)m0 * DIN) * 2;
    const char* bgh = (const char*)Bh + ((size_t)n0 * DIN) * 2;
    const char* bgl = (const char*)Bl + ((size_t)n0 * DIN) * 2;

    auto load = [&](int c, int st) {
        const uint32_t base = smb + st * STAGEB;
        const size_t cko = (size_t)c * KC * 2;       // 64B per chunk-row
        #pragma unroll
        for (int i = 0; i < 4; ++i) {
            int s   = tid + i * 128;                 // 0..511
            int r   = s >> 2;                        // row 0..127
            int seg = s & 3;                         // 16B segment
            size_t  go  = (size_t)r * (DIN * 2) + cko + seg * 16;
            uint32_t dof = r * PITCH + seg * 16;
            cp16(base + dof,              agh + go);
            cp16(base + TILEB + dof,      agl + go);
            cp16(base + 2 * TILEB + dof,  bgh + go);
            cp16(base + 3 * TILEB + dof,  bgl + go);
        }
    };

    float C[4][8][4] = {};

    const uint32_t aRow = wm + (lane & 15);
    const uint32_t aCol = (lane >> 4) * 16;
    const uint32_t bRow = wn + ((lane >> 4) << 3) + (lane & 7);
    const uint32_t bCol = ((lane >> 3) & 1) * 16;

    load(0, 0);
    cp_commit();

    for (int c = 0; c < DIN / KC; ++c) {
        const int st = c & 1;
        if (c + 1 < DIN / KC) { load(c + 1, st ^ 1); cp_commit(); cp_wait1(); }
        else                  { cp_wait0(); }
        __syncthreads();

        const uint32_t sA = smb + st * STAGEB;
        const uint32_t sB = sA + 2 * TILEB;

        #pragma unroll
        for (int ks = 0; ks < 2; ++ks) {
            uint32_t ah[4][4], al[4][4], bh[8][2], bl[8][2];
            #pragma unroll
            for (int i = 0; i < 4; ++i) {
                uint32_t ad = sA + (aRow + i * 16) * PITCH + ks * 32 + aCol;
                ldsm4(ah[i][0], ah[i][1], ah[i][2], ah[i][3], ad);
                ldsm4(al[i][0], al[i][1], al[i][2], al[i][3], ad + TILEB);
            }
            #pragma unroll
            for (int p = 0; p < 4; ++p) {
                uint32_t bd = sB + (bRow + p * 16) * PITCH + ks * 32 + bCol;
                ldsm4(bh[2*p][0], bh[2*p][1], bh[2*p+1][0], bh[2*p+1][1], bd);
                ldsm4(bl[2*p][0], bl[2*p][1], bl[2*p+1][0], bl[2*p+1][1], bd + TILEB);
            }
            #pragma unroll
            for (int i = 0; i < 4; ++i)
                #pragma unroll
                for (int j = 0; j < 8; ++j) {
                    mma16816(C[i][j], ah[i], bh[j]);
                    mma16816(C[i][j], ah[i], bl[j]);
                    mma16816(C[i][j], al[i], bh[j]);
                }
        }
        __syncthreads();
    }

    // ---- epilogue ----
    const int rr = lane >> 2;
    const int cc = (lane & 3) * 2;
    const float scl = (MODE == 0 && bz == 0) ? 0.1803368801111244f : 1.0f; // (1/8)*log2(e)
    #pragma unroll
    for (int i = 0; i < 4; ++i) {
        #pragma unroll
        for (int j = 0; j < 8; ++j) {
            int m1 = m0 + wm + i * 16 + rr;
            int m2 = m1 + 8;
            int n  = n0 + wn + j * 8 + cc;
            if (MODE == 0) {
                __nv_bfloat16* oh = (bz == 0) ? g_qh : (bz == 1) ? g_kh : g_vh;
                __nv_bfloat16* ol = (bz == 0) ? g_ql : (bz == 1) ? g_kl : g_vl;
                int head = n >> 6, hd = n & 63;
                #pragma unroll
                for (int half = 0; half < 2; ++half) {
                    int mm = half ? m2 : m1;
                    float v0 = C[i][j][half * 2] * scl, v1 = C[i][j][half * 2 + 1] * scl;
                    __nv_bfloat16 h0 = __float2bfloat16(v0), h1 = __float2bfloat16(v1);
                    float l0 = v0 - __bfloat162float(h0), l1 = v1 - __bfloat162float(h1);
                    int b = mm >> 11, s = mm & 2047;
                    size_t idx = (((size_t)(b * HH + head) * SS + s) * HD) + hd;
                    *(uint32_t*)&oh[idx] = pack2h(h0, h1);
                    *(uint32_t*)&ol[idx] = pack_bf16(l0, l1);
                }
            } else {
                float b0 = bias[n], b1 = bias[n + 1];
                *(float2*)&dout[(size_t)m1 * DOUT + n] = make_float2(C[i][j][0] + b0, C[i][j][1] + b1);
                *(float2*)&dout[(size_t)m2 * DOUT + n] = make_float2(C[i][j][2] + b0, C[i][j][3] + b1);
            }
        }
    }
}

// ---------------------------------------------------------------------------
// Tensor-core causal flash attention (bf16 hi/lo split, mma.sync).
// CTA: 64 queries x (b,h), 128 threads (4 warps x 16 rows).  Key tiles of 64,
// cp.async x2.  92KB smem + low regs -> 2 CTAs/SM (softmax/MMA overlap).
// ---------------------------------------------------------------------------
#define APITCH  144
#define QBYTES  (64 * APITCH)        // 9216
#define KVBYTES (64 * APITCH)        // 9216
#define OFF_ST  (2 * QBYTES)         // 18432
#define STG_B   (4 * KVBYTES)        // 36864
#define ATTN_SMEM (OFF_ST + 2 * STG_B)  // 92160

__global__ __launch_bounds__(128, 2) void attn_mma_kernel()
{
    extern __shared__ char smc[];
    const uint32_t smb = smem_u32(smc);

    const int tid  = threadIdx.x;
    const int lane = tid & 31;
    const int wid  = tid >> 5;
    const int qt   = (int)(gridDim.x - 1) - (int)blockIdx.x;  // heavy tiles first
    const int h    = blockIdx.y, b = blockIdx.z;
    const int wq   = wid * 16;

    const size_t bh = ((size_t)(b * HH + h)) * SS;
    const char* gqh = (const char*)(g_qh + (bh + (size_t)qt * 64) * HD);
    const char* gql = (const char*)(g_ql + (bh + (size_t)qt * 64) * HD);
    const char* gkh = (const char*)(g_kh + bh * HD);
    const char* gkl = (const char*)(g_kl + bh * HD);
    const char* gvh = (const char*)(g_vh + bh * HD);
    const char* gvl = (const char*)(g_vl + bh * HD);

    // Q tile (64 rows x 128B) hi/lo
    #pragma unroll
    for (int i = 0; i < 4; ++i) {
        int s = tid + i * 128;                 // 0..511
        int r = s >> 3, seg = s & 7;
        uint32_t doff = r * APITCH + seg * 16;
        size_t   goff = (size_t)r * 128 + seg * 16;
        cp16(smb + doff,          gqh + goff);
        cp16(smb + QBYTES + doff, gql + goff);
    }
    auto loadKV = [&](int jt, int st) {
        const uint32_t base = smb + OFF_ST + st * STG_B;
        const size_t g0 = (size_t)jt * 64 * 128;
        #pragma unroll
        for (int i = 0; i < 4; ++i) {
            int s = tid + i * 128;             // 0..511
            int r = s >> 3, seg = s & 7;
            uint32_t doff = r * APITCH + seg * 16;
            size_t   goff = g0 + (size_t)r * 128 + seg * 16;
            cp16(base + doff,               gkh + goff);
            cp16(base + KVBYTES + doff,     gkl + goff);
            cp16(base + 2 * KVBYTES + doff, gvh + goff);
            cp16(base + 3 * KVBYTES + doff, gvl + goff);
        }
    };
    loadKV(0, 0);
    cp_commit();

    uint32_t qh[4][4], ql[4][4];
    float O[8][4] = {};
    float m0 = -1e30f, m1 = -1e30f, l0 = 0.f, l1 = 0.f;

    const uint32_t aoff = (wq + (lane & 15)) * APITCH + (lane >> 4) * 16;
    const uint32_t krow = (((lane >> 4) << 3) + (lane & 7)) * APITCH + ((lane >> 3) & 1) * 16;
    const uint32_t vrow = (lane & 15) * APITCH + (lane >> 4) * 16;

    for (int jt = 0; jt <= qt; ++jt) {
        const int st = jt & 1;
        if (jt < qt) { loadKV(jt + 1, st ^ 1); cp_commit(); cp_wait1(); }
        else         { cp_wait0(); }
        __syncthreads();

        if (jt == 0) {
            #pragma unroll
            for (int f = 0; f < 4; ++f) {
                ldsm4(qh[f][0], qh[f][1], qh[f][2], qh[f][3], smb + aoff + f * 32);
                ldsm4(ql[f][0], ql[f][1], ql[f][2], ql[f][3], smb + QBYTES + aoff + f * 32);
            }
        }

        const uint32_t kb = smb + OFF_ST + st * STG_B;

        // ---- S = Q K^T (hi/lo 3-MMA split) ----
        float s_[8][4] = {};
        #pragma unroll
        for (int jp = 0; jp < 4; ++jp) {
            #pragma unroll
            for (int f = 0; f < 4; ++f) {
                uint32_t a = kb + krow + jp * 16 * APITCH + f * 32;
                uint32_t kh[4], kl[4];
                ldsm4(kh[0], kh[1], kh[2], kh[3], a);
                ldsm4(kl[0], kl[1], kl[2], kl[3], a + KVBYTES);
                mma16816(s_[2*jp],     qh[f], kh);
                mma16816(s_[2*jp],     ql[f], kh);
                mma16816(s_[2*jp],     qh[f], kl);
                mma16816(s_[2*jp + 1], qh[f], kh + 2);
                mma16816(s_[2*jp + 1], ql[f], kh + 2);
                mma16816(s_[2*jp + 1], qh[f], kl + 2);
            }
        }

        // ---- causal mask (diagonal tile only) ----
        if (jt == qt) {
            const int qrow  = qt * 64 + wq + (lane >> 2);
            const int kcol0 = jt * 64 + (lane & 3) * 2;
            #pragma unroll
            for (int j = 0; j < 8; ++j) {
                int c0 = kcol0 + j * 8, c1 = c0 + 1;
                if (c0 > qrow)     s_[j][0] = -1e30f;
                if (c1 > qrow)     s_[j][1] = -1e30f;
                if (c0 > qrow + 8) s_[j][2] = -1e30f;
                if (c1 > qrow + 8) s_[j][3] = -1e30f;
            }
        }

        // ---- online softmax (base-2; scale folded into Q) ----
        float mx0 = -1e30f, mx1 = -1e30f;
        #pragma unroll
        for (int j = 0; j < 8; ++j) {
            mx0 = fmaxf(mx0, fmaxf(s_[j][0], s_[j][1]));
            mx1 = fmaxf(mx1, fmaxf(s_[j][2], s_[j][3]));
        }
        mx0 = fmaxf(mx0, __shfl_xor_sync(0xffffffffu, mx0, 1));
        mx0 = fmaxf(mx0, __shfl_xor_sync(0xffffffffu, mx0, 2));
        mx1 = fmaxf(mx1, __shfl_xor_sync(0xffffffffu, mx1, 1));
        mx1 = fmaxf(mx1, __shfl_xor_sync(0xffffffffu, mx1, 2));
        float mn0 = fmaxf(m0, mx0), mn1 = fmaxf(m1, mx1);
        float c0 = exp2f(m0 - mn0), c1 = exp2f(m1 - mn1);
        m0 = mn0; m1 = mn1;
        float rs0 = 0.f, rs1 = 0.f;
        #pragma unroll
        for (int j = 0; j < 8; ++j) {
            s_[j][0] = exp2f(s_[j][0] - mn0);
            s_[j][1] = exp2f(s_[j][1] - mn0);
            s_[j][2] = exp2f(s_[j][2] - mn1);
            s_[j][3] = exp2f(s_[j][3] - mn1);
            rs0 += s_[j][0] + s_[j][1];
            rs1 += s_[j][2] + s_[j][3];
        }
        l0 = l0 * c0 + rs0;
        l1 = l1 * c1 + rs1;
        #pragma unroll
        for (int dj = 0; dj < 8; ++dj) {
            O[dj][0] *= c0; O[dj][1] *= c0;
            O[dj][2] *= c1; O[dj][3] *= c1;
        }

        // ---- O += P V (P from registers via C->A identity; hi/lo split) ----
        const uint32_t vb = kb + 2 * KVBYTES + vrow;
        #pragma unroll
        for (int f = 0; f < 4; ++f) {
            uint32_t ph[4], pl[4];
            #pragma unroll
            for (int t = 0; t < 2; ++t) {
                float p0 = s_[2*f + t][0], p1 = s_[2*f + t][1];
                float p2 = s_[2*f + t][2], p3 = s_[2*f + t][3];
                __nv_bfloat16 h0 = __float2bfloat16(p0), h1 = __float2bfloat16(p1);
                __nv_bfloat16 h2 = __float2bfloat16(p2), h3 = __float2bfloat16(p3);
                ph[2*t]   = pack2h(h0, h1);
                ph[2*t+1] = pack2h(h2, h3);
                pl[2*t]   = pack_bf16(p0 - __bfloat162float(h0), p1 - __bfloat162float(h1));
                pl[2*t+1] = pack_bf16(p2 - __bfloat162float(h2), p3 - __bfloat162float(h3));
            }
            const uint32_t va = vb + f * 16 * APITCH;
            #pragma unroll
            for (int dj = 0; dj < 4; ++dj) {
                uint32_t vh[4], vl[4];
                ldsm4t(vh[0], vh[1], vh[2], vh[3], va + dj * 32);
                ldsm4t(vl[0], vl[1], vl[2], vl[3], va + dj * 32 + KVBYTES);
                mma16816(O[2*dj],     ph, vh);
                mma16816(O[2*dj],     pl, vh);
                mma16816(O[2*dj],     ph, vl);
                mma16816(O[2*dj + 1], ph, vh + 2);
                mma16816(O[2*dj + 1], pl, vh + 2);
                mma16816(O[2*dj + 1], ph, vl + 2);
            }
        }
        __syncthreads();
    }

    // ---- finalize: reduce l over quad, normalize, write ctx hi/lo ----
    l0 += __shfl_xor_sync(0xffffffffu, l0, 1);
    l0 += __shfl_xor_sync(0xffffffffu, l0, 2);
    l1 += __shfl_xor_sync(0xffffffffu, l1, 1);
    l1 += __shfl_xor_sync(0xffffffffu, l1, 2);
    const float inv0 = 1.0f / l0, inv1 = 1.0f / l1;

    const int r    = lane >> 2;
    const int dcol = (lane & 3) * 2;
    const int row0 = qt * 64 + wq + r;
    const size_t base0 = ((size_t)b * SS + row0) * DOUT + h * 64;
    const size_t base1 = base0 + (size_t)8 * DOUT;
    #pragma unroll
    for (int dj = 0; dj < 8; ++dj) {
        int d = dj * 8 + dcol;
        {
            float v0 = O[dj][0] * inv0, v1 = O[dj][1] * inv0;
            __nv_bfloat16 h0 = __float2bfloat16(v0), h1 = __float2bfloat16(v1);
            *(uint32_t*)&g_cxh[base0 + d] = pack2h(h0, h1);
            *(uint32_t*)&g_cxl[base0 + d] =
                pack_bf16(v0 - __bfloat162float(h0), v1 - __bfloat162float(h1));
        }
        {
            float v2 = O[dj][2] * inv1, v3 = O[dj][3] * inv1;
            __nv_bfloat16 h2 = __float2bfloat16(v2), h3 = __float2bfloat16(v3);
            *(uint32_t*)&g_cxh[base1 + d] = pack2h(h2, h3);
            *(uint32_t*)&g_cxl[base1 + d] =
                pack_bf16(v2 - __bfloat162float(h2), v3 - __bfloat162float(h3));
        }
    }
}

// ---------------------------------------------------------------------------
extern "C" void kernel_launch(void* const* d_in, const int* in_sizes, int n_in,
                              void* d_out, int out_size)
{
    const float* x  = (const float*)d_in[0];
    const float* Wq = (const float*)d_in[1];
    const float* Wk = (const float*)d_in[2];
    const float* Wv = (const float*)d_in[3];
    const float* Wo = (const float*)d_in[4];
    const float* bo = (const float*)d_in[5];
    float* out = (float*)d_out;

    cudaFuncSetAttribute(mma_gemm<0>, cudaFuncAttributeMaxDynamicSharedMemorySize, GSMEM);
    cudaFuncSetAttribute(mma_gemm<1>, cudaFuncAttributeMaxDynamicSharedMemorySize, GSMEM);
    cudaFuncSetAttribute(attn_mma_kernel, cudaFuncAttributeMaxDynamicSharedMemorySize, ATTN_SMEM);

    conv_x_kernel<<<BB * SS * DIN / 1024, 256>>>(x);
    conv_w_kernel<<<dim3(32, 32, 4), dim3(32, 8)>>>(Wq, Wk, Wv, Wo);
    mma_gemm<0><<<dim3(64, 8, 3), 128, GSMEM>>>(nullptr, nullptr);
    attn_mma_kernel<<<dim3(32, HH, BB), 128, ATTN_SMEM>>>();
    mma_gemm<1><<<dim3(64, 8), 128, GSMEM>>>(bo, out);
}